// round 3
// baseline (speedup 1.0000x reference)
#include <cuda_runtime.h>
#include <math.h>

// NeRFAcc occupancy-grid sampler.
// Inputs (metadata order): origins [N,3] f32, directions [N,3] f32,
//   occs [128,128,128] f32, aabb [2,3] f32.
// Output (flattened tuple, float32):
//   positions [N,S,3] | t_starts [N,S] | t_ends [N,S] | ray_indices [N,S] | mask [N,S]

#define RESG 128
#define NSTEPS 320
#define STEPF 0.01f
#define ALPHA_THRE 0.01f

__global__ __launch_bounds__(256)
void nerfacc_sampler_kernel(const float* __restrict__ origins,
                            const float* __restrict__ dirs,
                            const float* __restrict__ occs,
                            const float* __restrict__ aabb,
                            float* __restrict__ out,
                            int N)
{
    const int CHUNKS = NSTEPS / 4;                 // 80 chunks of 4 steps
    int tid = blockIdx.x * blockDim.x + threadIdx.x;
    int total = N * CHUNKS;
    if (tid >= total) return;

    int ray = tid / CHUNKS;
    int s0  = (tid - ray * CHUNKS) * 4;

    // ---- per-ray data ----
    float ox = __ldg(origins + 3 * ray + 0);
    float oy = __ldg(origins + 3 * ray + 1);
    float oz = __ldg(origins + 3 * ray + 2);
    float dx = __ldg(dirs + 3 * ray + 0);
    float dy = __ldg(dirs + 3 * ray + 1);
    float dz = __ldg(dirs + 3 * ray + 2);

    float a0x = __ldg(aabb + 0), a0y = __ldg(aabb + 1), a0z = __ldg(aabb + 2);
    float a1x = __ldg(aabb + 3), a1y = __ldg(aabb + 4), a1z = __ldg(aabb + 5);

    // ---- robust slab intersection (matches reference) ----
    float sdx = (fabsf(dx) < 1e-10f) ? 1e-10f : dx;
    float sdy = (fabsf(dy) < 1e-10f) ? 1e-10f : dy;
    float sdz = (fabsf(dz) < 1e-10f) ? 1e-10f : dz;
    float ivx = 1.0f / sdx, ivy = 1.0f / sdy, ivz = 1.0f / sdz;

    float t0x = (a0x - ox) * ivx, t1x = (a1x - ox) * ivx;
    float t0y = (a0y - oy) * ivy, t1y = (a1y - oy) * ivy;
    float t0z = (a0z - oz) * ivz, t1z = (a1z - oz) * ivz;

    float tmin = fmaxf(fmaxf(fminf(t0x, t1x), fminf(t0y, t1y)), fminf(t0z, t1z));
    float tmax = fminf(fminf(fmaxf(t0x, t1x), fmaxf(t0y, t1y)), fmaxf(t0z, t1z));
    tmin = fmaxf(tmin, 0.0f);                      // NEAR = 0

    float invsx = 1.0f / (a1x - a0x);
    float invsy = 1.0f / (a1y - a0y);
    float invsz = 1.0f / (a1z - a0z);

    bool ray_ok = (tmax > tmin);

    // ---- 4 steps per thread ----
    float px[4], py[4], pz[4], ts[4], te[4], ri[4], mk[4];

    #pragma unroll
    for (int j = 0; j < 4; j++) {
        float s = (float)(s0 + j);
        float t_start = tmin + s * STEPF;
        float t_end   = t_start + STEPF;
        float t_mid   = 0.5f * (t_start + t_end);

        float x = fmaf(dx, t_mid, ox);
        float y = fmaf(dy, t_mid, oy);
        float z = fmaf(dz, t_mid, oz);

        float ux = (x - a0x) * invsx;
        float uy = (y - a0y) * invsy;
        float uz = (z - a0z) * invsz;

        int ix = (int)floorf(ux * (float)RESG);
        int iy = (int)floorf(uy * (float)RESG);
        int iz = (int)floorf(uz * (float)RESG);
        ix = min(max(ix, 0), RESG - 1);
        iy = min(max(iy, 0), RESG - 1);
        iz = min(max(iz, 0), RESG - 1);

        float occ = __ldg(occs + ((size_t)ix * RESG + iy) * RESG + iz);

        bool inside = (ux >= 0.0f) & (ux < 1.0f)
                    & (uy >= 0.0f) & (uy < 1.0f)
                    & (uz >= 0.0f) & (uz < 1.0f);

        float alpha = 1.0f - expf(-occ * STEPF);

        bool m = inside && (t_end <= tmax) && (alpha > ALPHA_THRE) && ray_ok;
        float mf = m ? 1.0f : 0.0f;

        px[j] = x * mf;
        py[j] = y * mf;
        pz[j] = z * mf;
        ts[j] = t_start * mf;
        te[j] = t_end * mf;
        ri[j] = m ? (float)ray : -1.0f;
        mk[j] = mf;
    }

    // ---- vectorized stores ----
    size_t NS  = (size_t)N * NSTEPS;
    size_t lin = (size_t)ray * NSTEPS + s0;

    // positions: 12 consecutive floats starting at lin*3 (48B-aligned)
    float* pbase = out + lin * 3;
    float4 v0 = make_float4(px[0], py[0], pz[0], px[1]);
    float4 v1 = make_float4(py[1], pz[1], px[2], py[2]);
    float4 v2 = make_float4(pz[2], px[3], py[3], pz[3]);
    reinterpret_cast<float4*>(pbase)[0] = v0;
    reinterpret_cast<float4*>(pbase)[1] = v1;
    reinterpret_cast<float4*>(pbase)[2] = v2;

    float* tstart_base = out + NS * 3 + lin;
    float* tend_base   = out + NS * 4 + lin;
    float* ridx_base   = out + NS * 5 + lin;
    float* mask_base   = out + NS * 6 + lin;

    *reinterpret_cast<float4*>(tstart_base) = make_float4(ts[0], ts[1], ts[2], ts[3]);
    *reinterpret_cast<float4*>(tend_base)   = make_float4(te[0], te[1], te[2], te[3]);
    *reinterpret_cast<float4*>(ridx_base)   = make_float4(ri[0], ri[1], ri[2], ri[3]);
    *reinterpret_cast<float4*>(mask_base)   = make_float4(mk[0], mk[1], mk[2], mk[3]);
}

extern "C" void kernel_launch(void* const* d_in, const int* in_sizes, int n_in,
                              void* d_out, int out_size)
{
    const float* origins = (const float*)d_in[0];
    const float* dirs    = (const float*)d_in[1];
    const float* occs    = (const float*)d_in[2];
    const float* aabb    = (const float*)d_in[3];
    float* out           = (float*)d_out;

    int N = in_sizes[0] / 3;
    int total = N * (NSTEPS / 4);
    int block = 256;
    int grid = (total + block - 1) / block;
    nerfacc_sampler_kernel<<<grid, block>>>(origins, dirs, occs, aabb, out, N);
}

// round 4
// speedup vs baseline: 1.1200x; 1.1200x over previous
#include <cuda_runtime.h>
#include <math.h>

// NeRFAcc occupancy-grid sampler.
// Inputs: origins [N,3] f32, directions [N,3] f32, occs [128^3] f32, aabb [2,3] f32.
// Output (flat f32): positions [N,S,3] | t_starts [N,S] | t_ends [N,S] | ray_idx [N,S] | mask [N,S]

#define RESG 128
#define NSTEPS 320
#define STEPF 0.01f
#define ALPHA_THRE 0.01f

__device__ __forceinline__ void stcs4(float* p, float a, float b, float c, float d) {
    float4 v = make_float4(a, b, c, d);
    __stcs(reinterpret_cast<float4*>(p), v);
}

__global__ __launch_bounds__(256, 8)
void nerfacc_sampler_kernel(const float* __restrict__ origins,
                            const float* __restrict__ dirs,
                            const float* __restrict__ occs,
                            const float* __restrict__ aabb,
                            float* __restrict__ out,
                            int N)
{
    const int CHUNKS = NSTEPS / 4;                 // 80 chunks of 4 steps
    int tid = blockIdx.x * blockDim.x + threadIdx.x;
    int total = N * CHUNKS;
    if (tid >= total) return;

    int ray = tid / CHUNKS;
    int s0  = (tid - ray * CHUNKS) * 4;

    // ---- per-ray data (broadcast within warp) ----
    float ox = __ldg(origins + 3 * ray + 0);
    float oy = __ldg(origins + 3 * ray + 1);
    float oz = __ldg(origins + 3 * ray + 2);
    float dx = __ldg(dirs + 3 * ray + 0);
    float dy = __ldg(dirs + 3 * ray + 1);
    float dz = __ldg(dirs + 3 * ray + 2);

    float a0x = __ldg(aabb + 0), a0y = __ldg(aabb + 1), a0z = __ldg(aabb + 2);
    float a1x = __ldg(aabb + 3), a1y = __ldg(aabb + 4), a1z = __ldg(aabb + 5);

    // ---- robust slab intersection (matches reference exactly) ----
    float sdx = (fabsf(dx) < 1e-10f) ? 1e-10f : dx;
    float sdy = (fabsf(dy) < 1e-10f) ? 1e-10f : dy;
    float sdz = (fabsf(dz) < 1e-10f) ? 1e-10f : dz;
    float ivx = 1.0f / sdx, ivy = 1.0f / sdy, ivz = 1.0f / sdz;

    float t0x = (a0x - ox) * ivx, t1x = (a1x - ox) * ivx;
    float t0y = (a0y - oy) * ivy, t1y = (a1y - oy) * ivy;
    float t0z = (a0z - oz) * ivz, t1z = (a1z - oz) * ivz;

    float tmin = fmaxf(fmaxf(fminf(t0x, t1x), fminf(t0y, t1y)), fminf(t0z, t1z));
    float tmax = fminf(fminf(fmaxf(t0x, t1x), fmaxf(t0y, t1y)), fmaxf(t0z, t1z));
    tmin = fmaxf(tmin, 0.0f);                      // NEAR = 0

    float invsx = 1.0f / (a1x - a0x);
    float invsy = 1.0f / (a1y - a0y);
    float invsz = 1.0f / (a1z - a0z);

    bool ray_ok = (tmax > tmin);

    // ---- phase 1: positions + predicated occ gathers ----
    float P[12];          // 4 x (x,y,z)
    float occv[4];
    unsigned premask = 0; // bit j: geometric mask (independent of occ)

    #pragma unroll
    for (int j = 0; j < 4; j++) {
        float t_start = fmaf((float)(s0 + j), STEPF, tmin);
        float t_end   = t_start + STEPF;
        float t_mid   = 0.5f * (t_start + t_end);

        float x = fmaf(dx, t_mid, ox);
        float y = fmaf(dy, t_mid, oy);
        float z = fmaf(dz, t_mid, oz);
        P[j * 3 + 0] = x;
        P[j * 3 + 1] = y;
        P[j * 3 + 2] = z;

        float ux = (x - a0x) * invsx;
        float uy = (y - a0y) * invsy;
        float uz = (z - a0z) * invsz;

        bool inside = (ux >= 0.0f) & (ux < 1.0f)
                    & (uy >= 0.0f) & (uy < 1.0f)
                    & (uz >= 0.0f) & (uz < 1.0f);

        bool pre = inside && (t_end <= tmax) && ray_ok;

        occv[j] = 0.0f;
        if (pre) {
            int ix = min(max((int)floorf(ux * (float)RESG), 0), RESG - 1);
            int iy = min(max((int)floorf(uy * (float)RESG), 0), RESG - 1);
            int iz = min(max((int)floorf(uz * (float)RESG), 0), RESG - 1);
            occv[j] = __ldg(occs + ((ix * RESG + iy) * RESG + iz));
            premask |= (1u << j);
        }
    }

    // ---- phase 2: final mask (alpha test) ----
    float mf[4];
    #pragma unroll
    for (int j = 0; j < 4; j++) {
        // alpha = 1 - exp(-occ*step) > thre  (occ=0 when pre==false -> alpha=0 -> false)
        float alpha = 1.0f - expf(-occv[j] * STEPF);
        bool m = ((premask >> j) & 1u) && (alpha > ALPHA_THRE);
        mf[j] = m ? 1.0f : 0.0f;
    }

    // ---- phase 3: streaming stores ----
    size_t NS  = (size_t)N * NSTEPS;
    size_t lin = (size_t)ray * NSTEPS + s0;

    // positions: 12 consecutive floats at lin*3 (48B-aligned -> three 16B stores)
    {
        float* pb = out + lin * 3;
        stcs4(pb + 0, P[0] * mf[0], P[1]  * mf[0], P[2]  * mf[0], P[3] * mf[1]);
        stcs4(pb + 4, P[4] * mf[1], P[5]  * mf[1], P[6]  * mf[2], P[7] * mf[2]);
        stcs4(pb + 8, P[8] * mf[2], P[9]  * mf[3], P[10] * mf[3], P[11] * mf[3]);
    }

    // t_starts / t_ends recomputed (cheap) instead of buffered
    {
        float t0 = fmaf((float)(s0 + 0), STEPF, tmin);
        float t1 = fmaf((float)(s0 + 1), STEPF, tmin);
        float t2 = fmaf((float)(s0 + 2), STEPF, tmin);
        float t3 = fmaf((float)(s0 + 3), STEPF, tmin);
        stcs4(out + NS * 3 + lin, t0 * mf[0], t1 * mf[1], t2 * mf[2], t3 * mf[3]);
        stcs4(out + NS * 4 + lin, (t0 + STEPF) * mf[0], (t1 + STEPF) * mf[1],
                                  (t2 + STEPF) * mf[2], (t3 + STEPF) * mf[3]);
    }

    float rf = (float)ray;
    stcs4(out + NS * 5 + lin,
          mf[0] != 0.0f ? rf : -1.0f,
          mf[1] != 0.0f ? rf : -1.0f,
          mf[2] != 0.0f ? rf : -1.0f,
          mf[3] != 0.0f ? rf : -1.0f);

    stcs4(out + NS * 6 + lin, mf[0], mf[1], mf[2], mf[3]);
}

extern "C" void kernel_launch(void* const* d_in, const int* in_sizes, int n_in,
                              void* d_out, int out_size)
{
    const float* origins = (const float*)d_in[0];
    const float* dirs    = (const float*)d_in[1];
    const float* occs    = (const float*)d_in[2];
    const float* aabb    = (const float*)d_in[3];
    float* out           = (float*)d_out;

    int N = in_sizes[0] / 3;
    int total = N * (NSTEPS / 4);
    int block = 256;
    int grid = (total + block - 1) / block;
    nerfacc_sampler_kernel<<<grid, block>>>(origins, dirs, occs, aabb, out, N);
}